// round 16
// baseline (speedup 1.0000x reference)
#include <cuda_runtime.h>
#include <cuda_fp16.h>
#include <cstdint>
#include <mma.h>
#include <math.h>

using namespace nvcuda;

#define TOKENS 16384
#define EMB    768
#define NH     12
#define HD     64
#define SLEN   1024
#define BATCH  16
#define MLPD   3072
#define NZ     (BATCH*NH)
#define QKVN   2304

// ---------------- scratch -----------------------------------------------
__device__ __half hW_qkv[EMB*QKVN];
__device__ __half hW_o[EMB*EMB];
__device__ __half hW_1[EMB*MLPD];
__device__ __half hW_2[MLPD*EMB];
__device__ float  g_bqkv[QKVN];
__device__ __half g_h  [TOKENS*EMB];
__device__ __half g_qkv[(size_t)TOKENS*QKVN];
__device__ __half g_ctx[TOKENS*EMB];
__device__ __half g_h2 [TOKENS*EMB];
__device__ __half g_m1 [TOKENS*MLPD];
__device__ float  g_x1 [TOKENS*EMB];

// ---------------- helpers -----------------------------------------------
__device__ __forceinline__ float gelu_exact(float x) {
    return 0.5f * x * (1.0f + erff(x * 0.70710678118654752440f));
}
__device__ __forceinline__ void cp16(void* dst, const void* src) {
    unsigned int s = (unsigned int)__cvta_generic_to_shared(dst);
    asm volatile("cp.async.cg.shared.global [%0], [%1], 16;\n" :: "r"(s), "l"(src));
}
#define CP_COMMIT()  asm volatile("cp.async.commit_group;\n" ::)
#define CP_WAIT(N)   asm volatile("cp.async.wait_group %0;\n" :: "n"(N))

#define MMA16816(d, a0, a1, a2, a3, b0, b1) \
    asm volatile("mma.sync.aligned.m16n8k16.row.col.f32.f16.f16.f32 " \
        "{%0,%1,%2,%3}, {%4,%5,%6,%7}, {%8,%9}, {%0,%1,%2,%3};" \
        : "+f"((d)[0]), "+f"((d)[1]), "+f"((d)[2]), "+f"((d)[3]) \
        : "r"(a0), "r"(a1), "r"(a2), "r"(a3), "r"(b0), "r"(b1))

#define LDSM_X4(r0, r1, r2, r3, addr) \
    asm volatile("ldmatrix.sync.aligned.m8n8.x4.shared.b16 {%0,%1,%2,%3}, [%4];" \
        : "=r"(r0), "=r"(r1), "=r"(r2), "=r"(r3) : "r"(addr))

#define LDSM_X4_T(r0, r1, r2, r3, addr) \
    asm volatile("ldmatrix.sync.aligned.m8n8.x4.trans.shared.b16 {%0,%1,%2,%3}, [%4];" \
        : "=r"(r0), "=r"(r1), "=r"(r2), "=r"(r3) : "r"(addr))

__device__ __forceinline__ uint32_t smem_u32(const void* p) {
    return (uint32_t)__cvta_generic_to_shared(p);
}

// fma-pipe exp2 (no MUFU). Valid for x <= ~30; clamps below -120.
// Max rel err ~2.4e-6 (deg-5 Taylor of e^u, |u| <= 0.347).
__device__ __forceinline__ float exp2c(float x) {
    x = fmaxf(x, -120.0f);
    float r = x + 12582912.0f;            // round-to-nearest-int trick (1.5*2^23)
    int   n = __float_as_int(r) - 0x4B400000;
    float f = x - (r - 12582912.0f);      // f in [-0.5, 0.5]
    float p = 1.3333558e-3f;
    p = fmaf(p, f, 9.6181291e-3f);
    p = fmaf(p, f, 5.5504109e-2f);
    p = fmaf(p, f, 2.4022651e-1f);
    p = fmaf(p, f, 6.9314718e-1f);
    p = fmaf(p, f, 1.0f);
    return p * __int_as_float((n + 127) << 23);
}

// ---------------- single prep kernel --------------------------------------
#define SQ   (EMB*EMB/4)
#define SMLP (EMB*MLPD/4)
#define PREP_TOTAL (3*SQ + SQ + 2*SMLP + QKVN/4)

__global__ __launch_bounds__(256) void prep_kernel(
    const float* __restrict__ Wq, const float* __restrict__ Wk,
    const float* __restrict__ Wv, const float* __restrict__ Wo,
    const float* __restrict__ W1, const float* __restrict__ W2,
    const float* __restrict__ bq, const float* __restrict__ bk,
    const float* __restrict__ bv,
    __half* __restrict__ pWqkv, __half* __restrict__ pWo,
    __half* __restrict__ pW1,  __half* __restrict__ pW2,
    float* __restrict__ pbqkv)
{
    int v = blockIdx.x * blockDim.x + threadIdx.x;
    if (v >= PREP_TOTAL) return;
    if (v < 3 * SQ) {
        int which = v / SQ, e = v % SQ;
        const float* W = which == 0 ? Wq : (which == 1 ? Wk : Wv);
        int i = e * 4;
        float4 x = *(const float4*)(W + i);
        int r = i / EMB, c = i % EMB;
        __half* o = pWqkv + (size_t)r * QKVN + which * EMB + c;
        *(__half2*)o       = __floats2half2_rn(x.x, x.y);
        *(__half2*)(o + 2) = __floats2half2_rn(x.z, x.w);
        return;
    }
    v -= 3 * SQ;
    if (v < SQ) {
        int i = v * 4;
        float4 x = *(const float4*)(Wo + i);
        *(__half2*)(pWo + i)     = __floats2half2_rn(x.x, x.y);
        *(__half2*)(pWo + i + 2) = __floats2half2_rn(x.z, x.w);
        return;
    }
    v -= SQ;
    if (v < SMLP) {
        int i = v * 4;
        float4 x = *(const float4*)(W1 + i);
        *(__half2*)(pW1 + i)     = __floats2half2_rn(x.x, x.y);
        *(__half2*)(pW1 + i + 2) = __floats2half2_rn(x.z, x.w);
        return;
    }
    v -= SMLP;
    if (v < SMLP) {
        int i = v * 4;
        float4 x = *(const float4*)(W2 + i);
        *(__half2*)(pW2 + i)     = __floats2half2_rn(x.x, x.y);
        *(__half2*)(pW2 + i + 2) = __floats2half2_rn(x.z, x.w);
        return;
    }
    v -= SMLP;
    {
        int i = v * 4;
        int which = i / EMB, j = i % EMB;
        const float* bsrc = which == 0 ? bq : (which == 1 ? bk : bv);
        float4 x = *(const float4*)(bsrc + j);
        *(float4*)(pbqkv + i) = x;
    }
}

// ---------------- LayerNorm (fp32 in, fp16 out) ---------------------------
__global__ __launch_bounds__(256) void ln_kernel(
    const float* __restrict__ x, const float* __restrict__ g,
    const float* __restrict__ b, __half* __restrict__ y)
{
    size_t row = blockIdx.x;
    const float* xr = x + row * EMB;
    int t = threadIdx.x;
    float v0 = xr[t], v1 = xr[t + 256], v2 = xr[t + 512];
    float s  = v0 + v1 + v2;
    float sq = v0*v0 + v1*v1 + v2*v2;
    __shared__ float red0[8], red1[8];
    #pragma unroll
    for (int o = 16; o; o >>= 1) {
        s  += __shfl_xor_sync(0xFFFFFFFFu, s,  o);
        sq += __shfl_xor_sync(0xFFFFFFFFu, sq, o);
    }
    int warp = t >> 5, lane = t & 31;
    if (lane == 0) { red0[warp] = s; red1[warp] = sq; }
    __syncthreads();
    float ts = 0.f, tq = 0.f;
    #pragma unroll
    for (int i = 0; i < 8; i++) { ts += red0[i]; tq += red1[i]; }
    float mu  = ts * (1.0f / EMB);
    float var = tq * (1.0f / EMB) - mu * mu;
    float rs  = rsqrtf(var + 1e-6f);
    __half* yr = y + row * EMB;
    yr[t]       = __float2half((v0 - mu) * rs * g[t]       + b[t]);
    yr[t + 256] = __float2half((v1 - mu) * rs * g[t + 256] + b[t + 256]);
    yr[t + 512] = __float2half((v2 - mu) * rs * g[t + 512] + b[t + 512]);
}

// ---------------- 2-stage BK=64 FP16 GEMM, warp tile 64x64 (R13) ----------
#define GEMM_SMEM 71680

template<int EPI>
__global__ __launch_bounds__(128, 2) void gemm_fp16_kernel(
    const __half* __restrict__ A, const __half* __restrict__ B,
    const float* __restrict__ bias, const float* __restrict__ R,
    void* __restrict__ Cv, int M, int N, int K)
{
    extern __shared__ __half smh[];
    int tid = threadIdx.x;
    int warp = tid >> 5, lane = tid & 31;
    int wr = warp >> 1, wc = warp & 1;
    int rowBase = blockIdx.y * 128;
    int colBase = blockIdx.x * 128;

    wmma::fragment<wmma::accumulator, 16, 16, 16, float> acc[4][4];
    #pragma unroll
    for (int f = 0; f < 4; f++)
        #pragma unroll
        for (int g = 0; g < 4; g++) wmma::fill_fragment(acc[f][g], 0.0f);

    auto load_stage = [&](int s, int k0) {
        __half* As = smh + s * 17920;
        __half* Bs = As + 9216;
        #pragma unroll
        for (int i = 0; i < 8; i++) {
            int idx = tid + i * 128;
            int r = idx >> 3, ch = idx & 7;
            cp16(As + r * 72 + ch * 8, A + (size_t)(rowBase + r) * K + k0 + ch * 8);
        }
        #pragma unroll
        for (int i = 0; i < 8; i++) {
            int idx = tid + i * 128;
            int r = idx >> 4, ch = idx & 15;
            cp16(Bs + r * 136 + ch * 8, B + (size_t)(k0 + r) * N + colBase + ch * 8);
        }
    };

    const int NS = K / 64;
    load_stage(0, 0);
    CP_COMMIT();

    for (int i = 0; i < NS; i++) {
        if (i + 1 < NS) {
            load_stage((i + 1) & 1, (i + 1) * 64);
            CP_COMMIT();
            CP_WAIT(1);
        } else {
            CP_WAIT(0);
        }
        __syncthreads();
        __half* As = smh + (i & 1) * 17920;
        __half* Bs = As + 9216;
        #pragma unroll
        for (int kk = 0; kk < 64; kk += 16) {
            wmma::fragment<wmma::matrix_a, 16, 16, 16, __half, wmma::row_major> af[4];
            wmma::fragment<wmma::matrix_b, 16, 16, 16, __half, wmma::row_major> bf[4];
            #pragma unroll
            for (int f = 0; f < 4; f++)
                wmma::load_matrix_sync(af[f], As + (wr * 64 + f * 16) * 72 + kk, 72);
            #pragma unroll
            for (int g = 0; g < 4; g++)
                wmma::load_matrix_sync(bf[g], Bs + kk * 136 + wc * 64 + g * 16, 136);
            #pragma unroll
            for (int f = 0; f < 4; f++)
                #pragma unroll
                for (int g = 0; g < 4; g++)
                    wmma::mma_sync(acc[f][g], af[f], bf[g], acc[f][g]);
        }
        __syncthreads();
    }

    float* stage = (float*)smh + warp * 320;
    #pragma unroll
    for (int f = 0; f < 4; f++) {
        #pragma unroll
        for (int g = 0; g < 4; g++) {
            wmma::store_matrix_sync(stage, acc[f][g], 20, wmma::mem_row_major);
            __syncwarp();
            int row0 = rowBase + wr * 64 + f * 16;
            int col0 = colBase + wc * 64 + g * 16;
            #pragma unroll
            for (int j = 0; j < 8; j++) {
                int e = lane + j * 32;
                int r = e >> 4, c = e & 15;
                float val = stage[r * 20 + c] + bias[col0 + c];
                if (EPI == 1) val = gelu_exact(val);
                size_t oidx = (size_t)(row0 + r) * N + (col0 + c);
                if (EPI == 2) {
                    ((float*)Cv)[oidx] = val + R[oidx];
                } else {
                    ((__half*)Cv)[oidx] = __float2half(val);
                }
            }
            __syncwarp();
        }
    }
}

// ------ register-resident flash attention (ldmatrix + fma-pipe exp2) ------
#define FLASH_SMEM 73728
// fold 1/sqrt(64)=0.125 and log2(e) into one scale: exp(s/8) = 2^(s*SCL)
#define SOFT_SCL 0.18033688f

__global__ __launch_bounds__(256) void flash_kernel(
    const __half* __restrict__ QKV, __half* __restrict__ Out)
{
    extern __shared__ __half fsh[];
    __half* Ks = fsh;            // 2 x 9216 halves
    __half* Vs = fsh + 18432;    // 2 x 9216 halves

    int z = blockIdx.y, b = z / NH, h = z % NH;
    int rowBase = blockIdx.x * 128;
    const __half* Qb = QKV + (size_t)b * SLEN * QKVN + h * HD;
    const __half* Kb = Qb + EMB;
    const __half* Vb = Qb + 2 * EMB;
    __half* Ob = Out + (size_t)b * SLEN * EMB + h * HD;

    int tid = threadIdx.x, warp = tid >> 5, lane = tid & 31;
    int qr = lane >> 2;
    int qc = (lane & 3) * 2;
    int rowin = lane & 7, grp = lane >> 3;
    int krow = (grp >> 1) * 8 + rowin;
    int kcol = (grp & 1) * 8;
    int vrow = (grp & 1) * 8 + rowin;
    int vcol = (grp >> 1) * 8;

    auto loadKV = [&](int buf, int kvBase) {
        __half* Kd = Ks + buf * 9216;
        __half* Vd = Vs + buf * 9216;
        #pragma unroll
        for (int i = 0; i < 4; i++) {
            int idx = tid + i * 256;
            int r = idx >> 3, ch = idx & 7;
            cp16(Kd + r * 72 + ch * 8, Kb + (size_t)(kvBase + r) * QKVN + ch * 8);
        }
        #pragma unroll
        for (int i = 0; i < 4; i++) {
            int idx = tid + i * 256;
            int r = idx >> 3, ch = idx & 7;
            cp16(Vd + r * 72 + ch * 8, Vb + (size_t)(kvBase + r) * QKVN + ch * 8);
        }
    };

    uint32_t qa[4][4];
    {
        const __half* q0 = Qb + (size_t)(rowBase + warp * 16 + qr) * QKVN;
        const __half* q8 = q0 + 8 * QKVN;
        #pragma unroll
        for (int kc = 0; kc < 4; kc++) {
            int k0 = kc * 16 + qc;
            qa[kc][0] = *(const uint32_t*)(q0 + k0);
            qa[kc][1] = *(const uint32_t*)(q8 + k0);
            qa[kc][2] = *(const uint32_t*)(q0 + k0 + 8);
            qa[kc][3] = *(const uint32_t*)(q8 + k0 + 8);
        }
    }

    loadKV(0, 0);
    CP_COMMIT();
    loadKV(1, 128);
    CP_COMMIT();

    float m0 = -1e30f, m1 = -1e30f, l0 = 0.f, l1 = 0.f;
    float ctx[8][4];
    #pragma unroll
    for (int n = 0; n < 8; n++) {
        ctx[n][0] = 0.f; ctx[n][1] = 0.f; ctx[n][2] = 0.f; ctx[n][3] = 0.f;
    }

    for (int kt = 0; kt < 8; kt++) {
        if (kt < 7) { CP_WAIT(1); } else { CP_WAIT(0); }
        __syncthreads();
        const __half* Kd = Ks + (kt & 1) * 9216;
        const __half* Vd = Vs + (kt & 1) * 9216;
        uint32_t ksb = smem_u32(Kd);
        uint32_t vsb = smem_u32(Vd);

        float s[16][4];
        #pragma unroll
        for (int nt = 0; nt < 16; nt++) {
            s[nt][0] = 0.f; s[nt][1] = 0.f; s[nt][2] = 0.f; s[nt][3] = 0.f;
        }
        #pragma unroll
        for (int kc = 0; kc < 4; kc++) {
            #pragma unroll
            for (int ntp = 0; ntp < 8; ntp++) {
                uint32_t addr = ksb + ((ntp * 16 + krow) * 72 + kc * 16 + kcol) * 2;
                uint32_t b0, b1, b2, b3;
                LDSM_X4(b0, b1, b2, b3, addr);
                MMA16816(s[2*ntp],   qa[kc][0], qa[kc][1], qa[kc][2], qa[kc][3], b0, b1);
                MMA16816(s[2*ntp+1], qa[kc][0], qa[kc][1], qa[kc][2], qa[kc][3], b2, b3);
            }
        }

        // online softmax in exp2 domain (scale folded)
        float mx0 = -1e30f, mx1 = -1e30f;
        #pragma unroll
        for (int nt = 0; nt < 16; nt++) {
            s[nt][0] *= SOFT_SCL; s[nt][1] *= SOFT_SCL;
            s[nt][2] *= SOFT_SCL; s[nt][3] *= SOFT_SCL;
            mx0 = fmaxf(mx0, fmaxf(s[nt][0], s[nt][1]));
            mx1 = fmaxf(mx1, fmaxf(s[nt][2], s[nt][3]));
        }
        mx0 = fmaxf(mx0, __shfl_xor_sync(0xFFFFFFFFu, mx0, 1));
        mx0 = fmaxf(mx0, __shfl_xor_sync(0xFFFFFFFFu, mx0, 2));
        mx1 = fmaxf(mx1, __shfl_xor_sync(0xFFFFFFFFu, mx1, 1));
        mx1 = fmaxf(mx1, __shfl_xor_sync(0xFFFFFFFFu, mx1, 2));
        float mn0 = fmaxf(m0, mx0), mn1 = fmaxf(m1, mx1);
        float al0 = exp2c(m0 - mn0), al1 = exp2c(m1 - mn1);
        m0 = mn0; m1 = mn1;

        float sum0 = 0.f, sum1 = 0.f;
        uint32_t pa[8][4];
        #pragma unroll
        for (int nt = 0; nt < 16; nt++) {
            s[nt][0] = exp2c(s[nt][0] - m0);
            s[nt][1] = exp2c(s[nt][1] - m0);
            s[nt][2] = exp2c(s[nt][2] - m1);
            s[nt][3] = exp2c(s[nt][3] - m1);
            sum0 += s[nt][0] + s[nt][1];
            sum1 += s[nt][2] + s[nt][3];
        }
        #pragma unroll
        for (int kc = 0; kc < 8; kc++) {
            __half2 h0 = __floats2half2_rn(s[2*kc][0],   s[2*kc][1]);
            __half2 h1 = __floats2half2_rn(s[2*kc][2],   s[2*kc][3]);
            __half2 h2 = __floats2half2_rn(s[2*kc+1][0], s[2*kc+1][1]);
            __half2 h3 = __floats2half2_rn(s[2*kc+1][2], s[2*kc+1][3]);
            pa[kc][0] = *(uint32_t*)&h0; pa[kc][1] = *(uint32_t*)&h1;
            pa[kc][2] = *(uint32_t*)&h2; pa[kc][3] = *(uint32_t*)&h3;
        }
        sum0 += __shfl_xor_sync(0xFFFFFFFFu, sum0, 1);
        sum0 += __shfl_xor_sync(0xFFFFFFFFu, sum0, 2);
        sum1 += __shfl_xor_sync(0xFFFFFFFFu, sum1, 1);
        sum1 += __shfl_xor_sync(0xFFFFFFFFu, sum1, 2);
        l0 = l0 * al0 + sum0;
        l1 = l1 * al1 + sum1;

        #pragma unroll
        for (int n = 0; n < 8; n++) {
            ctx[n][0] *= al0; ctx[n][1] *= al0;
            ctx[n][2] *= al1; ctx[n][3] *= al1;
        }

        #pragma unroll
        for (int kc = 0; kc < 8; kc++) {
            int kbase = kc * 16;
            #pragma unroll
            for (int ntp = 0; ntp < 4; ntp++) {
                uint32_t addr = vsb + ((kbase + vrow) * 72 + ntp * 16 + vcol) * 2;
                uint32_t b0, b1, b2, b3;
                LDSM_X4_T(b0, b1, b2, b3, addr);
                MMA16816(ctx[2*ntp],   pa[kc][0], pa[kc][1], pa[kc][2], pa[kc][3], b0, b1);
                MMA16816(ctx[2*ntp+1], pa[kc][0], pa[kc][1], pa[kc][2], pa[kc][3], b2, b3);
            }
        }

        __syncthreads();
        if (kt + 2 < 8) {
            loadKV(kt & 1, (kt + 2) * 128);
            CP_COMMIT();
        }
    }

    float inv0 = 1.0f / l0, inv1 = 1.0f / l1;
    __half* o0 = Ob + (size_t)(rowBase + warp * 16 + qr) * EMB + qc;
    __half* o8 = o0 + 8 * EMB;
    #pragma unroll
    for (int nt = 0; nt < 8; nt++) {
        *(__half2*)(o0 + nt * 8) = __floats2half2_rn(ctx[nt][0] * inv0, ctx[nt][1] * inv0);
        *(__half2*)(o8 + nt * 8) = __floats2half2_rn(ctx[nt][2] * inv1, ctx[nt][3] * inv1);
    }
}

// ---------------- launch --------------------------------------------------
extern "C" void kernel_launch(void* const* d_in, const int* in_sizes, int n_in,
                              void* d_out, int out_size)
{
    const float* x     = (const float*)d_in[0];
    const float* ln1_g = (const float*)d_in[1];
    const float* ln1_b = (const float*)d_in[2];
    const float* Wq    = (const float*)d_in[3];
    const float* bq    = (const float*)d_in[4];
    const float* Wk    = (const float*)d_in[5];
    const float* bk    = (const float*)d_in[6];
    const float* Wv    = (const float*)d_in[7];
    const float* bv    = (const float*)d_in[8];
    const float* Wo    = (const float*)d_in[9];
    const float* bo    = (const float*)d_in[10];
    const float* ln2_g = (const float*)d_in[11];
    const float* ln2_b = (const float*)d_in[12];
    const float* W1    = (const float*)d_in[13];
    const float* b1    = (const float*)d_in[14];
    const float* W2    = (const float*)d_in[15];
    const float* b2    = (const float*)d_in[16];
    float* out = (float*)d_out;

    __half *pWqkv, *pWo, *pW1, *pW2;
    __half *p_h, *p_qkv, *p_ctx, *p_h2, *p_m1;
    float  *p_x1, *p_bqkv;
    cudaGetSymbolAddress((void**)&pWqkv, hW_qkv);
    cudaGetSymbolAddress((void**)&pWo,   hW_o);
    cudaGetSymbolAddress((void**)&pW1,   hW_1);
    cudaGetSymbolAddress((void**)&pW2,   hW_2);
    cudaGetSymbolAddress((void**)&p_bqkv, g_bqkv);
    cudaGetSymbolAddress((void**)&p_h,   g_h);
    cudaGetSymbolAddress((void**)&p_qkv, g_qkv);
    cudaGetSymbolAddress((void**)&p_ctx, g_ctx);
    cudaGetSymbolAddress((void**)&p_h2,  g_h2);
    cudaGetSymbolAddress((void**)&p_m1,  g_m1);
    cudaGetSymbolAddress((void**)&p_x1,  g_x1);

    cudaFuncSetAttribute(gemm_fp16_kernel<0>, cudaFuncAttributeMaxDynamicSharedMemorySize, GEMM_SMEM);
    cudaFuncSetAttribute(gemm_fp16_kernel<1>, cudaFuncAttributeMaxDynamicSharedMemorySize, GEMM_SMEM);
    cudaFuncSetAttribute(gemm_fp16_kernel<2>, cudaFuncAttributeMaxDynamicSharedMemorySize, GEMM_SMEM);
    cudaFuncSetAttribute(flash_kernel,        cudaFuncAttributeMaxDynamicSharedMemorySize, FLASH_SMEM);

    prep_kernel<<<(PREP_TOTAL + 255) / 256, 256>>>(
        Wq, Wk, Wv, Wo, W1, W2, bq, bk, bv,
        pWqkv, pWo, pW1, pW2, p_bqkv);

    dim3 gQkv(QKVN / 128, TOKENS / 128);    // (18, 128)
    dim3 gProj(EMB / 128, TOKENS / 128);    // (6, 128)
    dim3 gMlp1(MLPD / 128, TOKENS / 128);   // (24, 128)

    ln_kernel<<<TOKENS, 256>>>(x, ln1_g, ln1_b, p_h);
    gemm_fp16_kernel<0><<<gQkv, 128, GEMM_SMEM>>>(p_h, pWqkv, p_bqkv, nullptr, p_qkv, TOKENS, QKVN, EMB);
    flash_kernel<<<dim3(SLEN / 128, NZ), 256, FLASH_SMEM>>>(p_qkv, p_ctx);
    gemm_fp16_kernel<2><<<gProj, 128, GEMM_SMEM>>>(p_ctx, pWo, bo, x, p_x1, TOKENS, EMB, EMB);
    ln_kernel<<<TOKENS, 256>>>(p_x1, ln2_g, ln2_b, p_h2);
    gemm_fp16_kernel<1><<<gMlp1, 128, GEMM_SMEM>>>(p_h2, pW1, b1, nullptr, p_m1, TOKENS, MLPD, EMB);
    gemm_fp16_kernel<2><<<gProj, 128, GEMM_SMEM>>>(p_m1, pW2, b2, p_x1, out, TOKENS, EMB, MLPD);
}

// round 17
// speedup vs baseline: 1.0481x; 1.0481x over previous
#include <cuda_runtime.h>
#include <cuda_fp16.h>
#include <cstdint>
#include <mma.h>
#include <math.h>

using namespace nvcuda;

#define TOKENS 16384
#define EMB    768
#define NH     12
#define HD     64
#define SLEN   1024
#define BATCH  16
#define MLPD   3072
#define NZ     (BATCH*NH)
#define QKVN   2304

// ---------------- scratch -----------------------------------------------
__device__ __half hW_qkv[EMB*QKVN];
__device__ __half hW_o[EMB*EMB];
__device__ __half hW_1[EMB*MLPD];
__device__ __half hW_2[MLPD*EMB];
__device__ float  g_bqkv[QKVN];
__device__ __half g_h  [TOKENS*EMB];
__device__ __half g_qkv[(size_t)TOKENS*QKVN];
__device__ __half g_ctx[TOKENS*EMB];
__device__ __half g_h2 [TOKENS*EMB];
__device__ __half g_m1 [TOKENS*MLPD];
__device__ float  g_x1 [TOKENS*EMB];

// ---------------- helpers -----------------------------------------------
__device__ __forceinline__ float gelu_exact(float x) {
    return 0.5f * x * (1.0f + erff(x * 0.70710678118654752440f));
}
__device__ __forceinline__ void cp16(void* dst, const void* src) {
    unsigned int s = (unsigned int)__cvta_generic_to_shared(dst);
    asm volatile("cp.async.cg.shared.global [%0], [%1], 16;\n" :: "r"(s), "l"(src));
}
#define CP_COMMIT()  asm volatile("cp.async.commit_group;\n" ::)
#define CP_WAIT(N)   asm volatile("cp.async.wait_group %0;\n" :: "n"(N))

#define MMA16816(d, a0, a1, a2, a3, b0, b1) \
    asm volatile("mma.sync.aligned.m16n8k16.row.col.f32.f16.f16.f32 " \
        "{%0,%1,%2,%3}, {%4,%5,%6,%7}, {%8,%9}, {%0,%1,%2,%3};" \
        : "+f"((d)[0]), "+f"((d)[1]), "+f"((d)[2]), "+f"((d)[3]) \
        : "r"(a0), "r"(a1), "r"(a2), "r"(a3), "r"(b0), "r"(b1))

#define LDSM_X4(r0, r1, r2, r3, addr) \
    asm volatile("ldmatrix.sync.aligned.m8n8.x4.shared.b16 {%0,%1,%2,%3}, [%4];" \
        : "=r"(r0), "=r"(r1), "=r"(r2), "=r"(r3) : "r"(addr))

#define LDSM_X4_T(r0, r1, r2, r3, addr) \
    asm volatile("ldmatrix.sync.aligned.m8n8.x4.trans.shared.b16 {%0,%1,%2,%3}, [%4];" \
        : "=r"(r0), "=r"(r1), "=r"(r2), "=r"(r3) : "r"(addr))

__device__ __forceinline__ uint32_t smem_u32(const void* p) {
    return (uint32_t)__cvta_generic_to_shared(p);
}

// ---------------- single prep kernel --------------------------------------
#define SQ   (EMB*EMB/4)
#define SMLP (EMB*MLPD/4)
#define PREP_TOTAL (3*SQ + SQ + 2*SMLP + QKVN/4)

__global__ __launch_bounds__(256) void prep_kernel(
    const float* __restrict__ Wq, const float* __restrict__ Wk,
    const float* __restrict__ Wv, const float* __restrict__ Wo,
    const float* __restrict__ W1, const float* __restrict__ W2,
    const float* __restrict__ bq, const float* __restrict__ bk,
    const float* __restrict__ bv,
    __half* __restrict__ pWqkv, __half* __restrict__ pWo,
    __half* __restrict__ pW1,  __half* __restrict__ pW2,
    float* __restrict__ pbqkv)
{
    int v = blockIdx.x * blockDim.x + threadIdx.x;
    if (v >= PREP_TOTAL) return;
    if (v < 3 * SQ) {
        int which = v / SQ, e = v % SQ;
        const float* W = which == 0 ? Wq : (which == 1 ? Wk : Wv);
        int i = e * 4;
        float4 x = *(const float4*)(W + i);
        int r = i / EMB, c = i % EMB;
        __half* o = pWqkv + (size_t)r * QKVN + which * EMB + c;
        *(__half2*)o       = __floats2half2_rn(x.x, x.y);
        *(__half2*)(o + 2) = __floats2half2_rn(x.z, x.w);
        return;
    }
    v -= 3 * SQ;
    if (v < SQ) {
        int i = v * 4;
        float4 x = *(const float4*)(Wo + i);
        *(__half2*)(pWo + i)     = __floats2half2_rn(x.x, x.y);
        *(__half2*)(pWo + i + 2) = __floats2half2_rn(x.z, x.w);
        return;
    }
    v -= SQ;
    if (v < SMLP) {
        int i = v * 4;
        float4 x = *(const float4*)(W1 + i);
        *(__half2*)(pW1 + i)     = __floats2half2_rn(x.x, x.y);
        *(__half2*)(pW1 + i + 2) = __floats2half2_rn(x.z, x.w);
        return;
    }
    v -= SMLP;
    if (v < SMLP) {
        int i = v * 4;
        float4 x = *(const float4*)(W2 + i);
        *(__half2*)(pW2 + i)     = __floats2half2_rn(x.x, x.y);
        *(__half2*)(pW2 + i + 2) = __floats2half2_rn(x.z, x.w);
        return;
    }
    v -= SMLP;
    {
        int i = v * 4;
        int which = i / EMB, j = i % EMB;
        const float* bsrc = which == 0 ? bq : (which == 1 ? bk : bv);
        float4 x = *(const float4*)(bsrc + j);
        *(float4*)(pbqkv + i) = x;
    }
}

// ---------------- LayerNorm (fp32 in, fp16 out) ---------------------------
__global__ __launch_bounds__(256) void ln_kernel(
    const float* __restrict__ x, const float* __restrict__ g,
    const float* __restrict__ b, __half* __restrict__ y)
{
    size_t row = blockIdx.x;
    const float* xr = x + row * EMB;
    int t = threadIdx.x;
    float v0 = xr[t], v1 = xr[t + 256], v2 = xr[t + 512];
    float s  = v0 + v1 + v2;
    float sq = v0*v0 + v1*v1 + v2*v2;
    __shared__ float red0[8], red1[8];
    #pragma unroll
    for (int o = 16; o; o >>= 1) {
        s  += __shfl_xor_sync(0xFFFFFFFFu, s,  o);
        sq += __shfl_xor_sync(0xFFFFFFFFu, sq, o);
    }
    int warp = t >> 5, lane = t & 31;
    if (lane == 0) { red0[warp] = s; red1[warp] = sq; }
    __syncthreads();
    float ts = 0.f, tq = 0.f;
    #pragma unroll
    for (int i = 0; i < 8; i++) { ts += red0[i]; tq += red1[i]; }
    float mu  = ts * (1.0f / EMB);
    float var = tq * (1.0f / EMB) - mu * mu;
    float rs  = rsqrtf(var + 1e-6f);
    __half* yr = y + row * EMB;
    yr[t]       = __float2half((v0 - mu) * rs * g[t]       + b[t]);
    yr[t + 256] = __float2half((v1 - mu) * rs * g[t + 256] + b[t + 256]);
    yr[t + 512] = __float2half((v2 - mu) * rs * g[t + 512] + b[t + 512]);
}

// ---------------- 2-stage BK=64 FP16 GEMM, warp tile 64x64 (R13) ----------
#define GEMM_SMEM 71680

template<int EPI>
__global__ __launch_bounds__(128, 2) void gemm_fp16_kernel(
    const __half* __restrict__ A, const __half* __restrict__ B,
    const float* __restrict__ bias, const float* __restrict__ R,
    void* __restrict__ Cv, int M, int N, int K)
{
    extern __shared__ __half smh[];
    int tid = threadIdx.x;
    int warp = tid >> 5, lane = tid & 31;
    int wr = warp >> 1, wc = warp & 1;
    int rowBase = blockIdx.y * 128;
    int colBase = blockIdx.x * 128;

    wmma::fragment<wmma::accumulator, 16, 16, 16, float> acc[4][4];
    #pragma unroll
    for (int f = 0; f < 4; f++)
        #pragma unroll
        for (int g = 0; g < 4; g++) wmma::fill_fragment(acc[f][g], 0.0f);

    auto load_stage = [&](int s, int k0) {
        __half* As = smh + s * 17920;
        __half* Bs = As + 9216;
        #pragma unroll
        for (int i = 0; i < 8; i++) {
            int idx = tid + i * 128;
            int r = idx >> 3, ch = idx & 7;
            cp16(As + r * 72 + ch * 8, A + (size_t)(rowBase + r) * K + k0 + ch * 8);
        }
        #pragma unroll
        for (int i = 0; i < 8; i++) {
            int idx = tid + i * 128;
            int r = idx >> 4, ch = idx & 15;
            cp16(Bs + r * 136 + ch * 8, B + (size_t)(k0 + r) * N + colBase + ch * 8);
        }
    };

    const int NS = K / 64;
    load_stage(0, 0);
    CP_COMMIT();

    for (int i = 0; i < NS; i++) {
        if (i + 1 < NS) {
            load_stage((i + 1) & 1, (i + 1) * 64);
            CP_COMMIT();
            CP_WAIT(1);
        } else {
            CP_WAIT(0);
        }
        __syncthreads();
        __half* As = smh + (i & 1) * 17920;
        __half* Bs = As + 9216;
        #pragma unroll
        for (int kk = 0; kk < 64; kk += 16) {
            wmma::fragment<wmma::matrix_a, 16, 16, 16, __half, wmma::row_major> af[4];
            wmma::fragment<wmma::matrix_b, 16, 16, 16, __half, wmma::row_major> bf[4];
            #pragma unroll
            for (int f = 0; f < 4; f++)
                wmma::load_matrix_sync(af[f], As + (wr * 64 + f * 16) * 72 + kk, 72);
            #pragma unroll
            for (int g = 0; g < 4; g++)
                wmma::load_matrix_sync(bf[g], Bs + kk * 136 + wc * 64 + g * 16, 136);
            #pragma unroll
            for (int f = 0; f < 4; f++)
                #pragma unroll
                for (int g = 0; g < 4; g++)
                    wmma::mma_sync(acc[f][g], af[f], bf[g], acc[f][g]);
        }
        __syncthreads();
    }

    float* stage = (float*)smh + warp * 320;
    #pragma unroll
    for (int f = 0; f < 4; f++) {
        #pragma unroll
        for (int g = 0; g < 4; g++) {
            wmma::store_matrix_sync(stage, acc[f][g], 20, wmma::mem_row_major);
            __syncwarp();
            int row0 = rowBase + wr * 64 + f * 16;
            int col0 = colBase + wc * 64 + g * 16;
            #pragma unroll
            for (int j = 0; j < 8; j++) {
                int e = lane + j * 32;
                int r = e >> 4, c = e & 15;
                float val = stage[r * 20 + c] + bias[col0 + c];
                if (EPI == 1) val = gelu_exact(val);
                size_t oidx = (size_t)(row0 + r) * N + (col0 + c);
                if (EPI == 2) {
                    ((float*)Cv)[oidx] = val + R[oidx];
                } else {
                    ((__half*)Cv)[oidx] = __float2half(val);
                }
            }
            __syncwarp();
        }
    }
}

// ------ register-resident flash attention (ldmatrix, 3-buffer KV ring) ----
// smem: K 3 x 9216 halves + V 3 x 9216 halves = 110592 B
#define FLASH_SMEM 110592

__global__ __launch_bounds__(256) void flash_kernel(
    const __half* __restrict__ QKV, __half* __restrict__ Out)
{
    extern __shared__ __half fsh[];
    __half* Ks = fsh;            // 3 x 9216 halves
    __half* Vs = fsh + 27648;    // 3 x 9216 halves

    int z = blockIdx.y, b = z / NH, h = z % NH;
    int rowBase = blockIdx.x * 128;
    const __half* Qb = QKV + (size_t)b * SLEN * QKVN + h * HD;
    const __half* Kb = Qb + EMB;
    const __half* Vb = Qb + 2 * EMB;
    __half* Ob = Out + (size_t)b * SLEN * EMB + h * HD;

    int tid = threadIdx.x, warp = tid >> 5, lane = tid & 31;
    int qr = lane >> 2;
    int qc = (lane & 3) * 2;
    int rowin = lane & 7, grp = lane >> 3;
    int krow = (grp >> 1) * 8 + rowin;
    int kcol = (grp & 1) * 8;
    int vrow = (grp & 1) * 8 + rowin;
    int vcol = (grp >> 1) * 8;

    auto loadKV = [&](int buf, int kvBase) {
        __half* Kd = Ks + buf * 9216;
        __half* Vd = Vs + buf * 9216;
        #pragma unroll
        for (int i = 0; i < 4; i++) {
            int idx = tid + i * 256;
            int r = idx >> 3, ch = idx & 7;
            cp16(Kd + r * 72 + ch * 8, Kb + (size_t)(kvBase + r) * QKVN + ch * 8);
        }
        #pragma unroll
        for (int i = 0; i < 4; i++) {
            int idx = tid + i * 256;
            int r = idx >> 3, ch = idx & 7;
            cp16(Vd + r * 72 + ch * 8, Vb + (size_t)(kvBase + r) * QKVN + ch * 8);
        }
    };

    uint32_t qa[4][4];
    {
        const __half* q0 = Qb + (size_t)(rowBase + warp * 16 + qr) * QKVN;
        const __half* q8 = q0 + 8 * QKVN;
        #pragma unroll
        for (int kc = 0; kc < 4; kc++) {
            int k0 = kc * 16 + qc;
            qa[kc][0] = *(const uint32_t*)(q0 + k0);
            qa[kc][1] = *(const uint32_t*)(q8 + k0);
            qa[kc][2] = *(const uint32_t*)(q0 + k0 + 8);
            qa[kc][3] = *(const uint32_t*)(q8 + k0 + 8);
        }
    }

    loadKV(0, 0);
    CP_COMMIT();
    loadKV(1, 128);
    CP_COMMIT();

    float m0 = -1e30f, m1 = -1e30f, l0 = 0.f, l1 = 0.f;
    float ctx[8][4];
    #pragma unroll
    for (int n = 0; n < 8; n++) {
        ctx[n][0] = 0.f; ctx[n][1] = 0.f; ctx[n][2] = 0.f; ctx[n][3] = 0.f;
    }

    for (int kt = 0; kt < 8; kt++) {
        if (kt < 7) { CP_WAIT(1); } else { CP_WAIT(0); }
        __syncthreads();
        // prefetch kt+2 into ring slot (kt+2)%3 — its prior readers (iter kt-1)
        // are fenced by the barrier above; no trailing sync needed.
        if (kt + 2 < 8) {
            loadKV((kt + 2) % 3, (kt + 2) * 128);
            CP_COMMIT();
        }
        const __half* Kd = Ks + (kt % 3) * 9216;
        const __half* Vd = Vs + (kt % 3) * 9216;
        uint32_t ksb = smem_u32(Kd);
        uint32_t vsb = smem_u32(Vd);

        float s[16][4];
        #pragma unroll
        for (int nt = 0; nt < 16; nt++) {
            s[nt][0] = 0.f; s[nt][1] = 0.f; s[nt][2] = 0.f; s[nt][3] = 0.f;
        }
        #pragma unroll
        for (int kc = 0; kc < 4; kc++) {
            #pragma unroll
            for (int ntp = 0; ntp < 8; ntp++) {
                uint32_t addr = ksb + ((ntp * 16 + krow) * 72 + kc * 16 + kcol) * 2;
                uint32_t b0, b1, b2, b3;
                LDSM_X4(b0, b1, b2, b3, addr);
                MMA16816(s[2*ntp],   qa[kc][0], qa[kc][1], qa[kc][2], qa[kc][3], b0, b1);
                MMA16816(s[2*ntp+1], qa[kc][0], qa[kc][1], qa[kc][2], qa[kc][3], b2, b3);
            }
        }

        float mx0 = -1e30f, mx1 = -1e30f;
        #pragma unroll
        for (int nt = 0; nt < 16; nt++) {
            s[nt][0] *= 0.125f; s[nt][1] *= 0.125f;
            s[nt][2] *= 0.125f; s[nt][3] *= 0.125f;
            mx0 = fmaxf(mx0, fmaxf(s[nt][0], s[nt][1]));
            mx1 = fmaxf(mx1, fmaxf(s[nt][2], s[nt][3]));
        }
        mx0 = fmaxf(mx0, __shfl_xor_sync(0xFFFFFFFFu, mx0, 1));
        mx0 = fmaxf(mx0, __shfl_xor_sync(0xFFFFFFFFu, mx0, 2));
        mx1 = fmaxf(mx1, __shfl_xor_sync(0xFFFFFFFFu, mx1, 1));
        mx1 = fmaxf(mx1, __shfl_xor_sync(0xFFFFFFFFu, mx1, 2));
        float mn0 = fmaxf(m0, mx0), mn1 = fmaxf(m1, mx1);
        float al0 = __expf(m0 - mn0), al1 = __expf(m1 - mn1);
        m0 = mn0; m1 = mn1;

        float sum0 = 0.f, sum1 = 0.f;
        uint32_t pa[8][4];
        #pragma unroll
        for (int nt = 0; nt < 16; nt++) {
            s[nt][0] = __expf(s[nt][0] - m0);
            s[nt][1] = __expf(s[nt][1] - m0);
            s[nt][2] = __expf(s[nt][2] - m1);
            s[nt][3] = __expf(s[nt][3] - m1);
            sum0 += s[nt][0] + s[nt][1];
            sum1 += s[nt][2] + s[nt][3];
        }
        #pragma unroll
        for (int kc = 0; kc < 8; kc++) {
            __half2 h0 = __floats2half2_rn(s[2*kc][0],   s[2*kc][1]);
            __half2 h1 = __floats2half2_rn(s[2*kc][2],   s[2*kc][3]);
            __half2 h2 = __floats2half2_rn(s[2*kc+1][0], s[2*kc+1][1]);
            __half2 h3 = __floats2half2_rn(s[2*kc+1][2], s[2*kc+1][3]);
            pa[kc][0] = *(uint32_t*)&h0; pa[kc][1] = *(uint32_t*)&h1;
            pa[kc][2] = *(uint32_t*)&h2; pa[kc][3] = *(uint32_t*)&h3;
        }
        sum0 += __shfl_xor_sync(0xFFFFFFFFu, sum0, 1);
        sum0 += __shfl_xor_sync(0xFFFFFFFFu, sum0, 2);
        sum1 += __shfl_xor_sync(0xFFFFFFFFu, sum1, 1);
        sum1 += __shfl_xor_sync(0xFFFFFFFFu, sum1, 2);
        l0 = l0 * al0 + sum0;
        l1 = l1 * al1 + sum1;

        #pragma unroll
        for (int n = 0; n < 8; n++) {
            ctx[n][0] *= al0; ctx[n][1] *= al0;
            ctx[n][2] *= al1; ctx[n][3] *= al1;
        }

        #pragma unroll
        for (int kc = 0; kc < 8; kc++) {
            int kbase = kc * 16;
            #pragma unroll
            for (int ntp = 0; ntp < 4; ntp++) {
                uint32_t addr = vsb + ((kbase + vrow) * 72 + ntp * 16 + vcol) * 2;
                uint32_t b0, b1, b2, b3;
                LDSM_X4_T(b0, b1, b2, b3, addr);
                MMA16816(ctx[2*ntp],   pa[kc][0], pa[kc][1], pa[kc][2], pa[kc][3], b0, b1);
                MMA16816(ctx[2*ntp+1], pa[kc][0], pa[kc][1], pa[kc][2], pa[kc][3], b2, b3);
            }
        }
    }

    float inv0 = 1.0f / l0, inv1 = 1.0f / l1;
    __half* o0 = Ob + (size_t)(rowBase + warp * 16 + qr) * EMB + qc;
    __half* o8 = o0 + 8 * EMB;
    #pragma unroll
    for (int nt = 0; nt < 8; nt++) {
        *(__half2*)(o0 + nt * 8) = __floats2half2_rn(ctx[nt][0] * inv0, ctx[nt][1] * inv0);
        *(__half2*)(o8 + nt * 8) = __floats2half2_rn(ctx[nt][2] * inv1, ctx[nt][3] * inv1);
    }
}

// ---------------- launch --------------------------------------------------
extern "C" void kernel_launch(void* const* d_in, const int* in_sizes, int n_in,
                              void* d_out, int out_size)
{
    const float* x     = (const float*)d_in[0];
    const float* ln1_g = (const float*)d_in[1];
    const float* ln1_b = (const float*)d_in[2];
    const float* Wq    = (const float*)d_in[3];
    const float* bq    = (const float*)d_in[4];
    const float* Wk    = (const float*)d_in[5];
    const float* bk    = (const float*)d_in[6];
    const float* Wv    = (const float*)d_in[7];
    const float* bv    = (const float*)d_in[8];
    const float* Wo    = (const float*)d_in[9];
    const float* bo    = (const float*)d_in[10];
    const float* ln2_g = (const float*)d_in[11];
    const float* ln2_b = (const float*)d_in[12];
    const float* W1    = (const float*)d_in[13];
    const float* b1    = (const float*)d_in[14];
    const float* W2    = (const float*)d_in[15];
    const float* b2    = (const float*)d_in[16];
    float* out = (float*)d_out;

    __half *pWqkv, *pWo, *pW1, *pW2;
    __half *p_h, *p_qkv, *p_ctx, *p_h2, *p_m1;
    float  *p_x1, *p_bqkv;
    cudaGetSymbolAddress((void**)&pWqkv, hW_qkv);
    cudaGetSymbolAddress((void**)&pWo,   hW_o);
    cudaGetSymbolAddress((void**)&pW1,   hW_1);
    cudaGetSymbolAddress((void**)&pW2,   hW_2);
    cudaGetSymbolAddress((void**)&p_bqkv, g_bqkv);
    cudaGetSymbolAddress((void**)&p_h,   g_h);
    cudaGetSymbolAddress((void**)&p_qkv, g_qkv);
    cudaGetSymbolAddress((void**)&p_ctx, g_ctx);
    cudaGetSymbolAddress((void**)&p_h2,  g_h2);
    cudaGetSymbolAddress((void**)&p_m1,  g_m1);
    cudaGetSymbolAddress((void**)&p_x1,  g_x1);

    cudaFuncSetAttribute(gemm_fp16_kernel<0>, cudaFuncAttributeMaxDynamicSharedMemorySize, GEMM_SMEM);
    cudaFuncSetAttribute(gemm_fp16_kernel<1>, cudaFuncAttributeMaxDynamicSharedMemorySize, GEMM_SMEM);
    cudaFuncSetAttribute(gemm_fp16_kernel<2>, cudaFuncAttributeMaxDynamicSharedMemorySize, GEMM_SMEM);
    cudaFuncSetAttribute(flash_kernel,        cudaFuncAttributeMaxDynamicSharedMemorySize, FLASH_SMEM);

    prep_kernel<<<(PREP_TOTAL + 255) / 256, 256>>>(
        Wq, Wk, Wv, Wo, W1, W2, bq, bk, bv,
        pWqkv, pWo, pW1, pW2, p_bqkv);

    dim3 gQkv(QKVN / 128, TOKENS / 128);    // (18, 128)
    dim3 gProj(EMB / 128, TOKENS / 128);    // (6, 128)
    dim3 gMlp1(MLPD / 128, TOKENS / 128);   // (24, 128)

    ln_kernel<<<TOKENS, 256>>>(x, ln1_g, ln1_b, p_h);
    gemm_fp16_kernel<0><<<gQkv, 128, GEMM_SMEM>>>(p_h, pWqkv, p_bqkv, nullptr, p_qkv, TOKENS, QKVN, EMB);
    flash_kernel<<<dim3(SLEN / 128, NZ), 256, FLASH_SMEM>>>(p_qkv, p_ctx);
    gemm_fp16_kernel<2><<<gProj, 128, GEMM_SMEM>>>(p_ctx, pWo, bo, x, p_x1, TOKENS, EMB, EMB);
    ln_kernel<<<TOKENS, 256>>>(p_x1, ln2_g, ln2_b, p_h2);
    gemm_fp16_kernel<1><<<gMlp1, 128, GEMM_SMEM>>>(p_h2, pW1, b1, nullptr, p_m1, TOKENS, MLPD, EMB);
    gemm_fp16_kernel<2><<<gProj, 128, GEMM_SMEM>>>(p_m1, pW2, b2, p_x1, out, TOKENS, EMB, MLPD);
}